// round 13
// baseline (speedup 1.0000x reference)
#include <cuda_runtime.h>
#include <cuda_fp16.h>
#include <stdint.h>

#define NB 8
#define NS 2048
#define ND 1024
#define NROWS (NB * NS)          // 16384
#define WSZ ((size_t)ND * ND)

// ---------------- scratch (no cudaMalloc allowed) ----------------
__device__ __half g_xn  [(size_t)NROWS * ND];
__device__ __half g_q   [(size_t)NROWS * ND];
__device__ __half g_k   [(size_t)NROWS * ND];
__device__ __half g_kT  [(size_t)NROWS * ND];
__device__ __half g_w   [(size_t)NB * NS * NS];
__device__ __half g_at  [(size_t)NROWS * ND];
__device__ float  g_x2  [(size_t)NROWS * ND];
__device__ __half g_xn2 [(size_t)NROWS * ND];
__device__ __half g_h   [(size_t)NROWS * ND];
__device__ __half g_wt  [5 * WSZ];   // 5 transposed fp16 weights

// ---------------- helpers ----------------
__device__ __forceinline__ uint32_t smem_u32(const void* p) {
    uint32_t a;
    asm("{ .reg .u64 t; cvta.to.shared.u64 t, %1; cvt.u32.u64 %0, t; }" : "=r"(a) : "l"(p));
    return a;
}
__device__ __forceinline__ void cp16(uint32_t dst, const void* src) {
    asm volatile("cp.async.cg.shared.global [%0], [%1], 16;" :: "r"(dst), "l"(src));
}
__device__ __forceinline__ void ldm4(uint32_t* a, uint32_t addr) {
    asm volatile("ldmatrix.sync.aligned.m8n8.x4.shared.b16 {%0,%1,%2,%3}, [%4];"
                 : "=r"(a[0]), "=r"(a[1]), "=r"(a[2]), "=r"(a[3]) : "r"(addr));
}
__device__ __forceinline__ void mma16816(float* c, const uint32_t* a, const uint32_t* b) {
    asm volatile("mma.sync.aligned.m16n8k16.row.col.f32.f16.f16.f32 "
                 "{%0,%1,%2,%3}, {%4,%5,%6,%7}, {%8,%9}, {%0,%1,%2,%3};"
                 : "+f"(c[0]), "+f"(c[1]), "+f"(c[2]), "+f"(c[3])
                 : "r"(a[0]), "r"(a[1]), "r"(a[2]), "r"(a[3]), "r"(b[0]), "r"(b[1]));
}

#define NSTG 3
#define STAGE 49152u               // A 16K (128 rows) | B 32K (256 rows), kchunk 64
#define SMEMSZ (NSTG * STAGE)      // 144 KB -> 1 CTA/SM
// A block: 16 row-tiles per kt8; B block: 32 row-tiles per kt8 (8x8 tiles, 128B)
__device__ __forceinline__ uint32_t toffA(int rt8, int kt8) {
    return (uint32_t)((kt8 * 16 + rt8) * 128);
}
__device__ __forceinline__ uint32_t toffB(int rt8, int kt8) {
    return (uint32_t)((kt8 * 32 + rt8) * 128);
}

// ---------------- warp-MMA fp16 GEMM: 128x256 CTA tile, kchunk 64, 1 pass ----------------
// 8 warps as 2(m) x 4(n), warp tile 64x64 (128 B of LDSM per MMA).
// D = alpha * A[M,K](fp16) * B[N,K]^T  (+bias) (mask==0 -> -1e9) (+resid) (relu)
// OUT: 0 = fp32, 1 = fp16
template <bool BIAS, bool RELU, bool MASK, bool RESID, int OUT>
__global__ void __launch_bounds__(256, 1) gemm_tc(
    const __half* __restrict__ A,
    const __half* __restrict__ B,
    int M, int N, int K,
    long long sA, long long sB, long long sC,
    float* __restrict__ Cf,
    __half* __restrict__ Ch,
    const float* __restrict__ bias,
    const float* __restrict__ resid,
    const int* __restrict__ mask,
    float alpha)
{
    extern __shared__ char smem[];
    const int tid  = threadIdx.x;
    const int lane = tid & 31, wid = tid >> 5;
    const int wm = wid & 1, wn = wid >> 1;          // 2 x 4 warp grid, warp tile 64x64
    const int bz = blockIdx.z;
    A += (size_t)bz * sA; B += (size_t)bz * sB;
    const size_t coff = (size_t)bz * sC;
    if (OUT == 0) Cf += coff; else Ch += coff;
    const int m0 = blockIdx.y * 128, n0 = blockIdx.x * 256;

    const uint32_t sb = smem_u32(smem);

    float acc[4][8][4];
#pragma unroll
    for (int i = 0; i < 4; i++)
#pragma unroll
        for (int j = 0; j < 8; j++)
#pragma unroll
            for (int q = 0; q < 4; q++) acc[i][j][q] = 0.f;

    const int nk = K >> 6;                           // 64-wide chunks

    // staging maps: vec idx -> row = idx>>3, kt8 = idx&7 (64 cols = 8 k-tiles)
    const int s_row = tid >> 3, s_kt = tid & 7;

    auto issue = [&](int i) {
        const uint32_t s = sb + (uint32_t)(i % NSTG) * STAGE;
        const int k0 = i << 6;
#pragma unroll
        for (int h = 0; h < 4; h++) {                // A: 128 rows
            const int r = s_row + h * 32;
            const uint32_t off = (uint32_t)((s_kt * 16 + (r >> 3)) * 128 + (r & 7) * 16);
            cp16(s + off, A + (size_t)(m0 + r) * K + k0 + s_kt * 8);
        }
#pragma unroll
        for (int h = 0; h < 8; h++) {                // B: 256 rows
            const int r = s_row + h * 32;
            const uint32_t off = (uint32_t)((s_kt * 32 + (r >> 3)) * 128 + (r & 7) * 16);
            cp16(s + 16384 + off, B + (size_t)(n0 + r) * K + k0 + s_kt * 8);
        }
        asm volatile("cp.async.commit_group;");
    };

    issue(0);
    issue(1);
    const int mrow16 = (lane & 7) * 16;
    const int dm = (lane >> 3) & 1, dk = lane >> 4;      // A x4 decode
    const int bksel = (lane >> 3) & 1, bnt = lane >> 4;  // B x4 decode (2 nt, 2 k-subtiles)

    for (int i = 0; i < nk; i++) {
        if (i == nk - 1) asm volatile("cp.async.wait_group 0;");
        else             asm volatile("cp.async.wait_group 1;");
        __syncthreads();
        if (i + 2 < nk) issue(i + 2);

        const uint32_t st  = sb + (uint32_t)(i % NSTG) * STAGE;
        const uint32_t sAa = st;
        const uint32_t sBb = st + 16384;

#pragma unroll
        for (int ks = 0; ks < 4; ks++) {             // 4 k16 subtiles per 64-chunk
            uint32_t a[4][4];
#pragma unroll
            for (int mt = 0; mt < 4; mt++) {
                const int mt8 = wm * 8 + mt * 2 + dm;
                ldm4(a[mt], sAa + toffA(mt8, ks * 2 + dk) + mrow16);
            }
            uint32_t b[8][2];
#pragma unroll
            for (int p = 0; p < 4; p++) {
                const int nt8 = wn * 8 + p * 2;
                uint32_t t[4];
                ldm4(t, sBb + toffB(nt8 + bnt, ks * 2 + bksel) + mrow16);
                b[p*2][0]   = t[0]; b[p*2][1]   = t[1];
                b[p*2+1][0] = t[2]; b[p*2+1][1] = t[3];
            }
            // 32 independent accumulators back-to-back
#pragma unroll
            for (int mt = 0; mt < 4; mt++)
#pragma unroll
                for (int nt = 0; nt < 8; nt++)
                    mma16816(acc[mt][nt], a[mt], b[nt]);
        }
    }

    // ---------------- epilogue ----------------
    const int cq = (lane & 3) * 2, rq = lane >> 2;
#pragma unroll
    for (int nt = 0; nt < 8; nt++) {
        const int c = n0 + wn * 64 + nt * 8 + cq;
        float bv0 = 0.f, bv1 = 0.f;
        if (BIAS) { bv0 = bias[c]; bv1 = bias[c + 1]; }
        int mk0 = 1, mk1 = 1;
        if (MASK) {
            const int* mp = mask + (size_t)bz * N;
            mk0 = mp[c]; mk1 = mp[c + 1];
        }
#pragma unroll
        for (int mt = 0; mt < 4; mt++) {
            const int r0 = m0 + wm * 64 + mt * 16 + rq;
#pragma unroll
            for (int h = 0; h < 2; h++) {
                const int row = r0 + h * 8;
                float v0 = acc[mt][nt][h * 2 + 0] * alpha + bv0;
                float v1 = acc[mt][nt][h * 2 + 1] * alpha + bv1;
                if (MASK) { if (mk0 == 0) v0 = -1e9f; if (mk1 == 0) v1 = -1e9f; }
                if (RESID) {
                    float2 rv = *(const float2*)(resid + (size_t)row * N + c);
                    v0 += rv.x; v1 += rv.y;
                }
                if (RELU) { v0 = fmaxf(v0, 0.f); v1 = fmaxf(v1, 0.f); }
                if (OUT == 0) {
                    *(float2*)(Cf + (size_t)row * N + c) = make_float2(v0, v1);
                } else {
                    *(__half2*)(Ch + (size_t)row * N + c) =
                        __halves2half2(__float2half(v0), __float2half(v1));
                }
            }
        }
    }
}

// ---------------- LayerNorm -> fp16 ----------------
__global__ void __launch_bounds__(256) ln_f16(const float* __restrict__ x,
                                              const float* __restrict__ g,
                                              const float* __restrict__ b,
                                              __half* __restrict__ o)
{
    size_t row = blockIdx.x;
    int t = threadIdx.x;
    float4 xv = ((const float4*)(x + row * ND))[t];
    float s  = xv.x + xv.y + xv.z + xv.w;
    float ss = xv.x*xv.x + xv.y*xv.y + xv.z*xv.z + xv.w*xv.w;
#pragma unroll
    for (int off = 16; off; off >>= 1) {
        s  += __shfl_xor_sync(0xffffffffu, s,  off);
        ss += __shfl_xor_sync(0xffffffffu, ss, off);
    }
    __shared__ float sh_s[8], sh_ss[8];
    if ((t & 31) == 0) { sh_s[t >> 5] = s; sh_ss[t >> 5] = ss; }
    __syncthreads();
    float ts = 0.f, tss = 0.f;
#pragma unroll
    for (int i = 0; i < 8; i++) { ts += sh_s[i]; tss += sh_ss[i]; }
    float mean = ts * (1.f / ND);
    float var  = tss * (1.f / ND) - mean * mean;
    float rstd = rsqrtf(var + 1e-5f);
    float4 gv = ((const float4*)g)[t];
    float4 bv = ((const float4*)b)[t];
    float o0 = (xv.x - mean) * rstd * gv.x + bv.x;
    float o1 = (xv.y - mean) * rstd * gv.y + bv.y;
    float o2 = (xv.z - mean) * rstd * gv.z + bv.z;
    float o3 = (xv.w - mean) * rstd * gv.w + bv.w;
    __half2* ph = (__half2*)(o + row * ND);
    ph[2*t]   = __halves2half2(__float2half(o0), __float2half(o1));
    ph[2*t+1] = __halves2half2(__float2half(o2), __float2half(o3));
}

// ---------------- softmax (fp32 in-place) + fp16 emission ----------------
__global__ void __launch_bounds__(256) softmax_f16(float* __restrict__ w,
                                                   __half* __restrict__ o)
{
    float* p = w + (size_t)blockIdx.x * NS;
    int t = threadIdx.x;
    float4 v0 = ((const float4*)p)[t];
    float4 v1 = ((const float4*)p)[t + 256];
    float mx = fmaxf(fmaxf(fmaxf(v0.x, v0.y), fmaxf(v0.z, v0.w)),
                     fmaxf(fmaxf(v1.x, v1.y), fmaxf(v1.z, v1.w)));
#pragma unroll
    for (int off = 16; off; off >>= 1) mx = fmaxf(mx, __shfl_xor_sync(0xffffffffu, mx, off));
    __shared__ float shm[8], shs[8];
    if ((t & 31) == 0) shm[t >> 5] = mx;
    __syncthreads();
    mx = shm[0];
#pragma unroll
    for (int i = 1; i < 8; i++) mx = fmaxf(mx, shm[i]);
    float e[8];
    e[0] = __expf(v0.x - mx); e[1] = __expf(v0.y - mx);
    e[2] = __expf(v0.z - mx); e[3] = __expf(v0.w - mx);
    e[4] = __expf(v1.x - mx); e[5] = __expf(v1.y - mx);
    e[6] = __expf(v1.z - mx); e[7] = __expf(v1.w - mx);
    float s = e[0]+e[1]+e[2]+e[3]+e[4]+e[5]+e[6]+e[7];
#pragma unroll
    for (int off = 16; off; off >>= 1) s += __shfl_xor_sync(0xffffffffu, s, off);
    if ((t & 31) == 0) shs[t >> 5] = s;
    __syncthreads();
    s = 0.f;
#pragma unroll
    for (int i = 0; i < 8; i++) s += shs[i];
    float inv = 1.f / s;
#pragma unroll
    for (int i = 0; i < 8; i++) e[i] *= inv;
    ((float4*)p)[t]       = make_float4(e[0], e[1], e[2], e[3]);
    ((float4*)p)[t + 256] = make_float4(e[4], e[5], e[6], e[7]);

    __half2* ph = (__half2*)(o + (size_t)blockIdx.x * NS);
    ph[2*t]         = __halves2half2(__float2half(e[0]), __float2half(e[1]));
    ph[2*t+1]       = __halves2half2(__float2half(e[2]), __float2half(e[3]));
    ph[512 + 2*t]   = __halves2half2(__float2half(e[4]), __float2half(e[5]));
    ph[512 + 2*t+1] = __halves2half2(__float2half(e[6]), __float2half(e[7]));
}

// ---------------- 5 weight transposes in ONE launch: W[K,N] fp32 -> WT[N,K] fp16 ----------------
__global__ void __launch_bounds__(256) wt_conv5(
    const float* __restrict__ W0, const float* __restrict__ W1,
    const float* __restrict__ W2, const float* __restrict__ W3,
    const float* __restrict__ W4, __half* __restrict__ T)
{
    const float* W;
    switch (blockIdx.z) {
        case 0: W = W0; break;
        case 1: W = W1; break;
        case 2: W = W2; break;
        case 3: W = W3; break;
        default: W = W4; break;
    }
    __half* Th = T + (size_t)blockIdx.z * WSZ;
    __shared__ float tile[64][65];
    int k0 = blockIdx.y * 64, n0 = blockIdx.x * 64;
#pragma unroll
    for (int u = threadIdx.x; u < 4096; u += 256) {
        int r = u >> 6, c = u & 63;
        tile[r][c] = W[(size_t)(k0 + r) * ND + n0 + c];
    }
    __syncthreads();
#pragma unroll
    for (int u = threadIdx.x; u < 4096; u += 256) {
        int r = u >> 6, c = u & 63;
        Th[(size_t)(n0 + r) * ND + k0 + c] = __float2half(tile[c][r]);
    }
}

// ---------------- fp16 transpose (k -> kT per batch) ----------------
__global__ void __launch_bounds__(256) kt_kernel(const __half* __restrict__ ih,
                                                 __half* __restrict__ oh)
{
    __shared__ __half th[64][65];
    int b = blockIdx.z;
    int d0 = blockIdx.x * 64, s0 = blockIdx.y * 64;
    const size_t ib = (size_t)b * NS * ND;
    const size_t ob = (size_t)b * ND * NS;
#pragma unroll
    for (int u = threadIdx.x; u < 4096; u += 256) {
        int r = u >> 6, c = u & 63;
        th[r][c] = ih[ib + (size_t)(s0 + r) * ND + d0 + c];
    }
    __syncthreads();
#pragma unroll
    for (int u = threadIdx.x; u < 4096; u += 256) {
        int r = u >> 6, c = u & 63;
        oh[ob + (size_t)(d0 + r) * NS + s0 + c] = th[c][r];
    }
}

// ---------------- driver ----------------
extern "C" void kernel_launch(void* const* d_in, const int* in_sizes, int n_in,
                              void* d_out, int out_size)
{
    const float* x    = (const float*)d_in[0];
    const int*   mask = (const int*)  d_in[1];
    const float* ln1g = (const float*)d_in[2];
    const float* ln1b = (const float*)d_in[3];
    const float* Wq   = (const float*)d_in[4];
    const float* bq   = (const float*)d_in[5];
    const float* Wk   = (const float*)d_in[6];
    const float* bk   = (const float*)d_in[7];
    const float* Wo   = (const float*)d_in[8];
    const float* bo   = (const float*)d_in[9];
    const float* ln2g = (const float*)d_in[10];
    const float* ln2b = (const float*)d_in[11];
    const float* W1   = (const float*)d_in[12];
    const float* b1   = (const float*)d_in[13];
    const float* W2   = (const float*)d_in[14];
    const float* b2   = (const float*)d_in[15];

    float* out  = (float*)d_out;
    float* wout = out + (size_t)NROWS * ND;

    __half *xn, *q, *k, *kT, *w, *at, *xn2, *h, *wt;
    float* x2;
    cudaGetSymbolAddress((void**)&xn,  g_xn);
    cudaGetSymbolAddress((void**)&q,   g_q);
    cudaGetSymbolAddress((void**)&k,   g_k);
    cudaGetSymbolAddress((void**)&kT,  g_kT);
    cudaGetSymbolAddress((void**)&w,   g_w);
    cudaGetSymbolAddress((void**)&at,  g_at);
    cudaGetSymbolAddress((void**)&xn2, g_xn2);
    cudaGetSymbolAddress((void**)&h,   g_h);
    cudaGetSymbolAddress((void**)&x2,  g_x2);
    cudaGetSymbolAddress((void**)&wt,  g_wt);

    __half *wq_t = wt + 0*WSZ;
    __half *wk_t = wt + 1*WSZ;
    __half *wo_t = wt + 2*WSZ;
    __half *w1_t = wt + 3*WSZ;
    __half *w2_t = wt + 4*WSZ;

    cudaFuncSetAttribute(gemm_tc<true,false,false,false,1>,
                         cudaFuncAttributeMaxDynamicSharedMemorySize, SMEMSZ);
    cudaFuncSetAttribute(gemm_tc<false,false,true,false,0>,
                         cudaFuncAttributeMaxDynamicSharedMemorySize, SMEMSZ);
    cudaFuncSetAttribute(gemm_tc<false,false,false,false,1>,
                         cudaFuncAttributeMaxDynamicSharedMemorySize, SMEMSZ);
    cudaFuncSetAttribute(gemm_tc<true,false,false,true,0>,
                         cudaFuncAttributeMaxDynamicSharedMemorySize, SMEMSZ);
    cudaFuncSetAttribute(gemm_tc<true,true,false,false,1>,
                         cudaFuncAttributeMaxDynamicSharedMemorySize, SMEMSZ);

    // all 5 weight transposes in one launch
    wt_conv5<<<dim3(16, 16, 5), 256>>>(Wq, Wk, Wo, W1, W2, wt);

    // 1) xn = LN1(x)
    ln_f16<<<NROWS, 256>>>(x, ln1g, ln1b, xn);

    dim3 gP(ND / 256, NROWS / 128, 1);
    // 2) q = xn@Wq+bq ; k = xn@Wk+bk  (v == k, faithful reference bug)
    gemm_tc<true,false,false,false,1><<<gP, 256, SMEMSZ>>>(
        xn, wq_t, NROWS, ND, ND, 0, 0, 0,
        nullptr, q, bq, nullptr, nullptr, 1.f);
    gemm_tc<true,false,false,false,1><<<gP, 256, SMEMSZ>>>(
        xn, wk_t, NROWS, ND, ND, 0, 0, 0,
        nullptr, k, bk, nullptr, nullptr, 1.f);

    // 3) kT for attn@v
    kt_kernel<<<dim3(ND / 64, NS / 64, NB), 256>>>(k, kT);

    // 4) scores = (q @ k^T)/32, masked -> wout (fp32)
    dim3 gS(NS / 256, NS / 128, NB);
    gemm_tc<false,false,true,false,0><<<gS, 256, SMEMSZ>>>(
        q, k, NS, NS, ND,
        (long long)NS * ND, (long long)NS * ND, (long long)NS * NS,
        wout, nullptr, nullptr, nullptr, mask, 0.03125f);

    // 5) softmax in place + fp16 w
    softmax_f16<<<NROWS, 256>>>(wout, w);

    // 6) attn = w @ v  (v == k)
    dim3 gA(ND / 256, NS / 128, NB);
    gemm_tc<false,false,false,false,1><<<gA, 256, SMEMSZ>>>(
        w, kT, NS, ND, NS,
        (long long)NS * NS, (long long)ND * NS, (long long)NS * ND,
        nullptr, at, nullptr, nullptr, nullptr, 1.f);

    // 7) x2 = x + attn @ Wo + bo
    gemm_tc<true,false,false,true,0><<<gP, 256, SMEMSZ>>>(
        at, wo_t, NROWS, ND, ND, 0, 0, 0,
        x2, nullptr, bo, x, nullptr, 1.f);

    // 8) xn2 = LN2(x2)
    ln_f16<<<NROWS, 256>>>(x2, ln2g, ln2b, xn2);

    // 9) h = relu(xn2 @ W1 + b1)
    gemm_tc<true,true,false,false,1><<<gP, 256, SMEMSZ>>>(
        xn2, w1_t, NROWS, ND, ND, 0, 0, 0,
        nullptr, h, b1, nullptr, nullptr, 1.f);

    // 10) out = x2 + h @ W2 + b2
    gemm_tc<true,false,false,true,0><<<gP, 256, SMEMSZ>>>(
        h, w2_t, NROWS, ND, ND, 0, 0, 0,
        out, nullptr, b2, x2, nullptr, 1.f);
}

// round 14
// speedup vs baseline: 1.2379x; 1.2379x over previous
#include <cuda_runtime.h>
#include <cuda_fp16.h>
#include <stdint.h>

#define NB 8
#define NS 2048
#define ND 1024
#define NROWS (NB * NS)          // 16384
#define WSZ ((size_t)ND * ND)

// ---------------- scratch (no cudaMalloc allowed) ----------------
__device__ __half g_xn  [(size_t)NROWS * ND];
__device__ __half g_q   [(size_t)NROWS * ND];
__device__ __half g_k   [(size_t)NROWS * ND];
__device__ __half g_kp  [(size_t)NROWS * ND];    // packed k rows (per batch)
__device__ __half g_ktp [(size_t)NROWS * ND];    // packed k transposed [ND x NS]
__device__ __half g_wp  [(size_t)NB * NS * NS];  // packed softmax fp16
__device__ __half g_at  [(size_t)NROWS * ND];
__device__ float  g_x2  [(size_t)NROWS * ND];
__device__ __half g_xn2 [(size_t)NROWS * ND];
__device__ __half g_h   [(size_t)NROWS * ND];
__device__ __half g_wt  [5 * WSZ];
__device__ int    g_idx [NB * NS];
__device__ int    g_pos [NB * NS];
__device__ int    g_cnt [NB];
__device__ int    g_cpd [NB];

// ---------------- helpers ----------------
__device__ __forceinline__ uint32_t smem_u32(const void* p) {
    uint32_t a;
    asm("{ .reg .u64 t; cvta.to.shared.u64 t, %1; cvt.u32.u64 %0, t; }" : "=r"(a) : "l"(p));
    return a;
}
__device__ __forceinline__ void cp16(uint32_t dst, const void* src) {
    asm volatile("cp.async.cg.shared.global [%0], [%1], 16;" :: "r"(dst), "l"(src));
}
__device__ __forceinline__ void ldmA(uint32_t* a, uint32_t addr) {
    asm volatile("ldmatrix.sync.aligned.m8n8.x4.shared.b16 {%0,%1,%2,%3}, [%4];"
                 : "=r"(a[0]), "=r"(a[1]), "=r"(a[2]), "=r"(a[3]) : "r"(addr));
}
__device__ __forceinline__ void ldmB(uint32_t* b, uint32_t addr) {
    asm volatile("ldmatrix.sync.aligned.m8n8.x2.shared.b16 {%0,%1}, [%2];"
                 : "=r"(b[0]), "=r"(b[1]) : "r"(addr));
}
__device__ __forceinline__ void mma16816(float* c, const uint32_t* a, const uint32_t* b) {
    asm volatile("mma.sync.aligned.m16n8k16.row.col.f32.f16.f16.f32 "
                 "{%0,%1,%2,%3}, {%4,%5,%6,%7}, {%8,%9}, {%0,%1,%2,%3};"
                 : "+f"(c[0]), "+f"(c[1]), "+f"(c[2]), "+f"(c[3])
                 : "r"(a[0]), "r"(a[1]), "r"(a[2]), "r"(a[3]), "r"(b[0]), "r"(b[1]));
}

#define NSTG 3
#define STAGE 32768u               // A 16K | B 16K  (kchunk = 64)
#define SMEMSZ (NSTG * STAGE)      // 96 KB -> 2 CTAs/SM
__device__ __forceinline__ uint32_t toff(int rt8, int kt8) {
    return (uint32_t)((kt8 * 16 + rt8) * 128);
}

// ---------------- warp-MMA fp16 GEMM: 128x128 CTA tile, kchunk 64, 1 pass ----------------
// D = alpha * A[M,K](fp16) * B[N,K]^T  (+bias) (+resid) (relu)
// OUT: 0=fp32, 1=fp16.  NCAPQ: skip blocks with n0 >= ncap[bz].  KCAPQ: K loop = kcap[bz].
template <bool BIAS, bool RELU, bool RESID, int OUT, bool NCAPQ, bool KCAPQ>
__global__ void __launch_bounds__(256, 2) gemm_tc(
    const __half* __restrict__ A,
    const __half* __restrict__ B,
    int M, int N, int K,
    long long sA, long long sB, long long sC,
    float* __restrict__ Cf,
    __half* __restrict__ Ch,
    const float* __restrict__ bias,
    const float* __restrict__ resid,
    const int* __restrict__ ncap,
    const int* __restrict__ kcap,
    float alpha)
{
    extern __shared__ char smem[];
    const int tid  = threadIdx.x;
    const int lane = tid & 31, wid = tid >> 5;
    const int wm = wid & 1, wn = wid >> 1;          // 2 x 4 warp grid, warp tile 64x32
    const int bz = blockIdx.z;
    const int n0 = blockIdx.x * 128;
    if (NCAPQ && n0 >= ncap[bz]) return;
    A += (size_t)bz * sA; B += (size_t)bz * sB;
    const size_t coff = (size_t)bz * sC;
    if (OUT == 0) Cf += coff; else Ch += coff;
    const int m0 = blockIdx.y * 128;

    const uint32_t sb = smem_u32(smem);

    float acc[4][4][4];
#pragma unroll
    for (int i = 0; i < 4; i++)
#pragma unroll
        for (int j = 0; j < 4; j++)
#pragma unroll
            for (int q = 0; q < 4; q++) acc[i][j][q] = 0.f;

    const int Keff = KCAPQ ? kcap[bz] : K;
    const int nk = Keff >> 6;                        // 64-wide chunks

    const int s_row = tid >> 3, s_kt = tid & 7;
    uint32_t doff[4];
    int      srow[4];
#pragma unroll
    for (int h = 0; h < 4; h++) {
        const int r = s_row + h * 32;
        srow[h] = r;
        doff[h] = (uint32_t)((s_kt * 16 + (r >> 3)) * 128 + (r & 7) * 16);
    }

    auto issue = [&](int i) {
        const uint32_t s = sb + (uint32_t)(i % NSTG) * STAGE;
        const int k0 = i << 6;
#pragma unroll
        for (int h = 0; h < 4; h++) {
            const size_t ga = (size_t)(m0 + srow[h]) * K + k0 + s_kt * 8;
            const size_t gb = (size_t)(n0 + srow[h]) * K + k0 + s_kt * 8;
            cp16(s + doff[h],         A + ga);
            cp16(s + 16384 + doff[h], B + gb);
        }
        asm volatile("cp.async.commit_group;");
    };

    issue(0);
    issue(1);
    const int mrow16 = (lane & 7) * 16;
    const int bmi = (lane >> 3) & 1;
    const int dm = (lane >> 3) & 1, dk = lane >> 4;

    for (int i = 0; i < nk; i++) {
        if (i == nk - 1) asm volatile("cp.async.wait_group 0;");
        else             asm volatile("cp.async.wait_group 1;");
        __syncthreads();
        if (i + 2 < nk) issue(i + 2);

        const uint32_t st  = sb + (uint32_t)(i % NSTG) * STAGE;
        const uint32_t sAa = st;
        const uint32_t sBb = st + 16384;

#pragma unroll
        for (int ks = 0; ks < 4; ks++) {
            uint32_t a[4][4];
#pragma unroll
            for (int mt = 0; mt < 4; mt++) {
                const int mt8 = wm * 8 + mt * 2 + dm;
                ldmA(a[mt], sAa + toff(mt8, ks * 2 + dk) + mrow16);
            }
            uint32_t bh[4][2];
#pragma unroll
            for (int nt = 0; nt < 4; nt++)
                ldmB(bh[nt], sBb + toff(wn * 4 + nt, ks * 2 + bmi) + mrow16);
#pragma unroll
            for (int mt = 0; mt < 4; mt++)
#pragma unroll
                for (int nt = 0; nt < 4; nt++)
                    mma16816(acc[mt][nt], a[mt], bh[nt]);
        }
    }

    // ---------------- epilogue ----------------
    const int cq = (lane & 3) * 2, rq = lane >> 2;
#pragma unroll
    for (int nt = 0; nt < 4; nt++) {
        const int c = n0 + wn * 32 + nt * 8 + cq;
        float bv0 = 0.f, bv1 = 0.f;
        if (BIAS) { bv0 = bias[c]; bv1 = bias[c + 1]; }
#pragma unroll
        for (int mt = 0; mt < 4; mt++) {
            const int r0 = m0 + wm * 64 + mt * 16 + rq;
#pragma unroll
            for (int h = 0; h < 2; h++) {
                const int row = r0 + h * 8;
                float v0 = acc[mt][nt][h * 2 + 0] * alpha + bv0;
                float v1 = acc[mt][nt][h * 2 + 1] * alpha + bv1;
                if (RESID) {
                    float2 rv = *(const float2*)(resid + (size_t)row * N + c);
                    v0 += rv.x; v1 += rv.y;
                }
                if (RELU) { v0 = fmaxf(v0, 0.f); v1 = fmaxf(v1, 0.f); }
                if (OUT == 0) {
                    *(float2*)(Cf + (size_t)row * N + c) = make_float2(v0, v1);
                } else {
                    *(__half2*)(Ch + (size_t)row * N + c) =
                        __halves2half2(__float2half(v0), __float2half(v1));
                }
            }
        }
    }
}

// ---------------- mask prefix scan: idx / pos / cnt / cnt_pad per batch ----------------
__global__ void __launch_bounds__(1024) mask_scan(const int* __restrict__ mask,
                                                  int* __restrict__ idx,
                                                  int* __restrict__ pos,
                                                  int* __restrict__ cnt,
                                                  int* __restrict__ cpd)
{
    __shared__ int sc[1024];
    const int b = blockIdx.x, t = threadIdx.x;
    const int m0 = mask[b * NS + 2 * t];
    const int m1 = mask[b * NS + 2 * t + 1];
    const int s = m0 + m1;
    sc[t] = s;
    __syncthreads();
    for (int off = 1; off < 1024; off <<= 1) {
        int v = (t >= off) ? sc[t - off] : 0;
        __syncthreads();
        sc[t] += v;
        __syncthreads();
    }
    const int ex = sc[t] - s;
    pos[b * NS + 2 * t]     = ex;
    pos[b * NS + 2 * t + 1] = ex + m0;
    if (m0) idx[b * NS + ex]      = 2 * t;
    if (m1) idx[b * NS + ex + m0] = 2 * t + 1;
    if (t == 1023) {
        cnt[b] = sc[1023];
        cpd[b] = (sc[1023] + 127) & ~127;
    }
}

// ---------------- gather packed k + transposed packed k ----------------
__global__ void __launch_bounds__(256) gather_k(const __half* __restrict__ k,
                                                const int* __restrict__ idx,
                                                const int* __restrict__ cnt,
                                                const int* __restrict__ cpd,
                                                __half* __restrict__ kp,
                                                __half* __restrict__ ktp)
{
    __shared__ __half tile[64][65];
    const int b = blockIdx.z;
    const int p0 = blockIdx.y * 64, d0 = blockIdx.x * 64;
    const int c = cnt[b], cp = cpd[b];
    if (p0 >= cp) return;
    const size_t kb  = (size_t)b * NS * ND;
    const size_t ktb = (size_t)b * ND * NS;
    const int* ib = idx + b * NS;
    for (int u = threadIdx.x; u < 4096; u += 256) {
        const int rr = u >> 6, cc = u & 63;
        const int p = p0 + rr;
        __half v = __float2half(0.f);
        if (p < c) v = k[kb + (size_t)ib[p] * ND + d0 + cc];
        tile[rr][cc] = v;
        kp[kb + (size_t)p * ND + d0 + cc] = v;
    }
    __syncthreads();
    for (int u = threadIdx.x; u < 4096; u += 256) {
        const int rr = u >> 6, cc = u & 63;
        ktp[ktb + (size_t)(d0 + rr) * NS + p0 + cc] = tile[cc][rr];
    }
}

// ---------------- softmax over packed scores + scatter to full w + packed fp16 ----------------
__global__ void __launch_bounds__(256) softmax_scatter(
    float* __restrict__ wout,
    __half* __restrict__ wp,
    const int* __restrict__ mask,
    const int* __restrict__ pos,
    const int* __restrict__ cnt,
    const int* __restrict__ cpd)
{
    __shared__ float sm[NS];
    __shared__ float red[8];
    const int r = blockIdx.x;
    const int b = r >> 11;
    const int t = threadIdx.x;
    const int c = cnt[b], cp = cpd[b];
    float* p = wout + (size_t)r * NS;

    float mx = -3.4e38f;
    for (int j = t; j < c; j += 256) mx = fmaxf(mx, p[j]);
#pragma unroll
    for (int o = 16; o; o >>= 1) mx = fmaxf(mx, __shfl_xor_sync(0xffffffffu, mx, o));
    if ((t & 31) == 0) red[t >> 5] = mx;
    __syncthreads();
    mx = red[0];
#pragma unroll
    for (int i = 1; i < 8; i++) mx = fmaxf(mx, red[i]);
    __syncthreads();

    float s = 0.f;
    for (int j = t; j < c; j += 256) {
        const float e = __expf(p[j] - mx);
        sm[j] = e;
        s += e;
    }
#pragma unroll
    for (int o = 16; o; o >>= 1) s += __shfl_xor_sync(0xffffffffu, s, o);
    if ((t & 31) == 0) red[t >> 5] = s;
    __syncthreads();
    s = 0.f;
#pragma unroll
    for (int i = 0; i < 8; i++) s += red[i];
    const float inv = 1.f / s;

    __half* wpr = wp + (size_t)r * NS;
    for (int j = t; j < cp; j += 256)
        wpr[j] = __float2half(j < c ? sm[j] * inv : 0.f);

    const int* mrow = mask + (size_t)b * NS;
    const int* prow = pos  + (size_t)b * NS;
    for (int j = t; j < NS; j += 256)
        p[j] = mrow[j] ? sm[prow[j]] * inv : 0.f;
}

// ---------------- LayerNorm -> fp16 ----------------
__global__ void __launch_bounds__(256) ln_f16(const float* __restrict__ x,
                                              const float* __restrict__ g,
                                              const float* __restrict__ b,
                                              __half* __restrict__ o)
{
    size_t row = blockIdx.x;
    int t = threadIdx.x;
    float4 xv = ((const float4*)(x + row * ND))[t];
    float s  = xv.x + xv.y + xv.z + xv.w;
    float ss = xv.x*xv.x + xv.y*xv.y + xv.z*xv.z + xv.w*xv.w;
#pragma unroll
    for (int off = 16; off; off >>= 1) {
        s  += __shfl_xor_sync(0xffffffffu, s,  off);
        ss += __shfl_xor_sync(0xffffffffu, ss, off);
    }
    __shared__ float sh_s[8], sh_ss[8];
    if ((t & 31) == 0) { sh_s[t >> 5] = s; sh_ss[t >> 5] = ss; }
    __syncthreads();
    float ts = 0.f, tss = 0.f;
#pragma unroll
    for (int i = 0; i < 8; i++) { ts += sh_s[i]; tss += sh_ss[i]; }
    float mean = ts * (1.f / ND);
    float var  = tss * (1.f / ND) - mean * mean;
    float rstd = rsqrtf(var + 1e-5f);
    float4 gv = ((const float4*)g)[t];
    float4 bv = ((const float4*)b)[t];
    float o0 = (xv.x - mean) * rstd * gv.x + bv.x;
    float o1 = (xv.y - mean) * rstd * gv.y + bv.y;
    float o2 = (xv.z - mean) * rstd * gv.z + bv.z;
    float o3 = (xv.w - mean) * rstd * gv.w + bv.w;
    __half2* ph = (__half2*)(o + row * ND);
    ph[2*t]   = __halves2half2(__float2half(o0), __float2half(o1));
    ph[2*t+1] = __halves2half2(__float2half(o2), __float2half(o3));
}

// ---------------- 5 weight transposes in ONE launch ----------------
__global__ void __launch_bounds__(256) wt_conv5(
    const float* __restrict__ W0, const float* __restrict__ W1,
    const float* __restrict__ W2, const float* __restrict__ W3,
    const float* __restrict__ W4, __half* __restrict__ T)
{
    const float* W;
    switch (blockIdx.z) {
        case 0: W = W0; break;
        case 1: W = W1; break;
        case 2: W = W2; break;
        case 3: W = W3; break;
        default: W = W4; break;
    }
    __half* Th = T + (size_t)blockIdx.z * WSZ;
    __shared__ float tile[64][65];
    int k0 = blockIdx.y * 64, n0 = blockIdx.x * 64;
#pragma unroll
    for (int u = threadIdx.x; u < 4096; u += 256) {
        int r = u >> 6, c = u & 63;
        tile[r][c] = W[(size_t)(k0 + r) * ND + n0 + c];
    }
    __syncthreads();
#pragma unroll
    for (int u = threadIdx.x; u < 4096; u += 256) {
        int r = u >> 6, c = u & 63;
        Th[(size_t)(n0 + r) * ND + k0 + c] = __float2half(tile[c][r]);
    }
}

// ---------------- driver ----------------
extern "C" void kernel_launch(void* const* d_in, const int* in_sizes, int n_in,
                              void* d_out, int out_size)
{
    const float* x    = (const float*)d_in[0];
    const int*   mask = (const int*)  d_in[1];
    const float* ln1g = (const float*)d_in[2];
    const float* ln1b = (const float*)d_in[3];
    const float* Wq   = (const float*)d_in[4];
    const float* bq   = (const float*)d_in[5];
    const float* Wk   = (const float*)d_in[6];
    const float* bk   = (const float*)d_in[7];
    const float* Wo   = (const float*)d_in[8];
    const float* bo   = (const float*)d_in[9];
    const float* ln2g = (const float*)d_in[10];
    const float* ln2b = (const float*)d_in[11];
    const float* W1   = (const float*)d_in[12];
    const float* b1   = (const float*)d_in[13];
    const float* W2   = (const float*)d_in[14];
    const float* b2   = (const float*)d_in[15];

    float* out  = (float*)d_out;
    float* wout = out + (size_t)NROWS * ND;

    __half *xn, *q, *k, *kp, *ktp, *wp, *at, *xn2, *h, *wt;
    float* x2;
    int *idx, *pos, *cnt, *cpd;
    cudaGetSymbolAddress((void**)&xn,  g_xn);
    cudaGetSymbolAddress((void**)&q,   g_q);
    cudaGetSymbolAddress((void**)&k,   g_k);
    cudaGetSymbolAddress((void**)&kp,  g_kp);
    cudaGetSymbolAddress((void**)&ktp, g_ktp);
    cudaGetSymbolAddress((void**)&wp,  g_wp);
    cudaGetSymbolAddress((void**)&at,  g_at);
    cudaGetSymbolAddress((void**)&xn2, g_xn2);
    cudaGetSymbolAddress((void**)&h,   g_h);
    cudaGetSymbolAddress((void**)&x2,  g_x2);
    cudaGetSymbolAddress((void**)&wt,  g_wt);
    cudaGetSymbolAddress((void**)&idx, g_idx);
    cudaGetSymbolAddress((void**)&pos, g_pos);
    cudaGetSymbolAddress((void**)&cnt, g_cnt);
    cudaGetSymbolAddress((void**)&cpd, g_cpd);

    __half *wq_t = wt + 0*WSZ;
    __half *wk_t = wt + 1*WSZ;
    __half *wo_t = wt + 2*WSZ;
    __half *w1_t = wt + 3*WSZ;
    __half *w2_t = wt + 4*WSZ;

    cudaFuncSetAttribute(gemm_tc<true,false,false,1,false,false>,
                         cudaFuncAttributeMaxDynamicSharedMemorySize, SMEMSZ);
    cudaFuncSetAttribute(gemm_tc<false,false,false,0,true,false>,
                         cudaFuncAttributeMaxDynamicSharedMemorySize, SMEMSZ);
    cudaFuncSetAttribute(gemm_tc<false,false,false,1,false,true>,
                         cudaFuncAttributeMaxDynamicSharedMemorySize, SMEMSZ);
    cudaFuncSetAttribute(gemm_tc<true,false,true,0,false,false>,
                         cudaFuncAttributeMaxDynamicSharedMemorySize, SMEMSZ);
    cudaFuncSetAttribute(gemm_tc<true,true,false,1,false,false>,
                         cudaFuncAttributeMaxDynamicSharedMemorySize, SMEMSZ);

    // weight transposes + mask scan (independent of GEMMs)
    wt_conv5<<<dim3(16, 16, 5), 256>>>(Wq, Wk, Wo, W1, W2, wt);
    mask_scan<<<NB, 1024>>>(mask, idx, pos, cnt, cpd);

    // 1) xn = LN1(x)
    ln_f16<<<NROWS, 256>>>(x, ln1g, ln1b, xn);

    dim3 gP(ND / 128, NROWS / 128, 1);
    // 2) q = xn@Wq+bq ; k = xn@Wk+bk  (v == k, faithful reference bug)
    gemm_tc<true,false,false,1,false,false><<<gP, 256, SMEMSZ>>>(
        xn, wq_t, NROWS, ND, ND, 0, 0, 0,
        nullptr, q, bq, nullptr, nullptr, nullptr, 1.f);
    gemm_tc<true,false,false,1,false,false><<<gP, 256, SMEMSZ>>>(
        xn, wk_t, NROWS, ND, ND, 0, 0, 0,
        nullptr, k, bk, nullptr, nullptr, nullptr, 1.f);

    // 3) packed k + packed kT (mask compaction)
    gather_k<<<dim3(ND / 64, NS / 64, NB), 256>>>(k, idx, cnt, cpd, kp, ktp);

    // 4) packed scores = (q @ kp^T)/32 -> wout packed cols (fp32)
    dim3 gS(NS / 128, NS / 128, NB);
    gemm_tc<false,false,false,0,true,false><<<gS, 256, SMEMSZ>>>(
        q, kp, NS, NS, ND,
        (long long)NS * ND, (long long)NS * ND, (long long)NS * NS,
        wout, nullptr, nullptr, nullptr, cpd, nullptr, 0.03125f);

    // 5) softmax over packed + scatter full w + packed fp16 w
    softmax_scatter<<<NROWS, 256>>>(wout, wp, mask, pos, cnt, cpd);

    // 6) attn = wp @ ktp^T  (K = cnt_pad per batch)
    dim3 gA(ND / 128, NS / 128, NB);
    gemm_tc<false,false,false,1,false,true><<<gA, 256, SMEMSZ>>>(
        wp, ktp, NS, ND, NS,
        (long long)NS * NS, (long long)ND * NS, (long long)NS * ND,
        nullptr, at, nullptr, nullptr, nullptr, cpd, 1.f);

    // 7) x2 = x + attn @ Wo + bo
    gemm_tc<true,false,true,0,false,false><<<gP, 256, SMEMSZ>>>(
        at, wo_t, NROWS, ND, ND, 0, 0, 0,
        x2, nullptr, bo, x, nullptr, nullptr, 1.f);

    // 8) xn2 = LN2(x2)
    ln_f16<<<NROWS, 256>>>(x2, ln2g, ln2b, xn2);

    // 9) h = relu(xn2 @ W1 + b1)
    gemm_tc<true,true,false,1,false,false><<<gP, 256, SMEMSZ>>>(
        xn2, w1_t, NROWS, ND, ND, 0, 0, 0,
        nullptr, h, b1, nullptr, nullptr, nullptr, 1.f);

    // 10) out = x2 + h @ W2 + b2
    gemm_tc<true,false,true,0,false,false><<<gP, 256, SMEMSZ>>>(
        h, w2_t, NROWS, ND, ND, 0, 0, 0,
        out, nullptr, b2, x2, nullptr, nullptr, 1.f);
}

// round 15
// speedup vs baseline: 1.2933x; 1.0448x over previous
#include <cuda_runtime.h>
#include <cuda_fp16.h>
#include <stdint.h>

#define NB 8
#define NS 2048
#define ND 1024
#define NROWS (NB * NS)          // 16384
#define WSZ ((size_t)ND * ND)

// ---------------- scratch (no cudaMalloc allowed) ----------------
__device__ __half g_xn  [(size_t)NROWS * ND];
__device__ __half g_xnp [(size_t)NROWS * ND];    // packed xn rows (per batch)
__device__ __half g_q   [(size_t)NROWS * ND];
__device__ __half g_kp  [(size_t)NROWS * ND];    // packed k rows (per batch)
__device__ __half g_ktp [(size_t)NROWS * ND];    // packed k transposed [ND x NS]
__device__ __half g_wp  [(size_t)NB * NS * NS];  // packed softmax fp16
__device__ __half g_at  [(size_t)NROWS * ND];
__device__ float  g_x2  [(size_t)NROWS * ND];
__device__ __half g_xn2 [(size_t)NROWS * ND];
__device__ __half g_h   [(size_t)NROWS * ND];
__device__ __half g_wt  [5 * WSZ];
__device__ int    g_idx [NB * NS];
__device__ int    g_pos [NB * NS];
__device__ int    g_cnt [NB];
__device__ int    g_cpd [NB];

// ---------------- helpers ----------------
__device__ __forceinline__ uint32_t smem_u32(const void* p) {
    uint32_t a;
    asm("{ .reg .u64 t; cvta.to.shared.u64 t, %1; cvt.u32.u64 %0, t; }" : "=r"(a) : "l"(p));
    return a;
}
__device__ __forceinline__ void cp16(uint32_t dst, const void* src) {
    asm volatile("cp.async.cg.shared.global [%0], [%1], 16;" :: "r"(dst), "l"(src));
}
__device__ __forceinline__ void ldmA(uint32_t* a, uint32_t addr) {
    asm volatile("ldmatrix.sync.aligned.m8n8.x4.shared.b16 {%0,%1,%2,%3}, [%4];"
                 : "=r"(a[0]), "=r"(a[1]), "=r"(a[2]), "=r"(a[3]) : "r"(addr));
}
__device__ __forceinline__ void ldmB(uint32_t* b, uint32_t addr) {
    asm volatile("ldmatrix.sync.aligned.m8n8.x2.shared.b16 {%0,%1}, [%2];"
                 : "=r"(b[0]), "=r"(b[1]) : "r"(addr));
}
__device__ __forceinline__ void mma16816(float* c, const uint32_t* a, const uint32_t* b) {
    asm volatile("mma.sync.aligned.m16n8k16.row.col.f32.f16.f16.f32 "
                 "{%0,%1,%2,%3}, {%4,%5,%6,%7}, {%8,%9}, {%0,%1,%2,%3};"
                 : "+f"(c[0]), "+f"(c[1]), "+f"(c[2]), "+f"(c[3])
                 : "r"(a[0]), "r"(a[1]), "r"(a[2]), "r"(a[3]), "r"(b[0]), "r"(b[1]));
}

#define NSTG 3
#define STAGE 32768u               // A 16K | B 16K  (kchunk = 64)
#define SMEMSZ (NSTG * STAGE)      // 96 KB -> 2 CTAs/SM
__device__ __forceinline__ uint32_t toff(int rt8, int kt8) {
    return (uint32_t)((kt8 * 16 + rt8) * 128);
}

// ---------------- warp-MMA fp16 GEMM: 128x128 CTA tile, kchunk 64, 1 pass ----------------
// D = alpha * A[M,K](fp16) * B[N,K]^T  (+bias) (+resid) (relu)
// OUT: 0=fp32, 1=fp16.
// NCAPQ: skip blocks with n0 >= ncap[bz].  KCAPQ: K loop = kcap[bz].  MCAPQ: skip m0 >= mcap[bz].
template <bool BIAS, bool RELU, bool RESID, int OUT, bool NCAPQ, bool KCAPQ, bool MCAPQ>
__global__ void __launch_bounds__(256, 2) gemm_tc(
    const __half* __restrict__ A,
    const __half* __restrict__ B,
    int M, int N, int K,
    long long sA, long long sB, long long sC,
    float* __restrict__ Cf,
    __half* __restrict__ Ch,
    const float* __restrict__ bias,
    const float* __restrict__ resid,
    const int* __restrict__ ncap,
    const int* __restrict__ kcap,
    const int* __restrict__ mcap,
    float alpha)
{
    extern __shared__ char smem[];
    const int tid  = threadIdx.x;
    const int lane = tid & 31, wid = tid >> 5;
    const int wm = wid & 1, wn = wid >> 1;          // 2 x 4 warp grid, warp tile 64x32
    const int bz = blockIdx.z;
    const int n0 = blockIdx.x * 128;
    const int m0 = blockIdx.y * 128;
    if (NCAPQ && n0 >= ncap[bz]) return;
    if (MCAPQ && m0 >= mcap[bz]) return;
    A += (size_t)bz * sA; B += (size_t)bz * sB;
    const size_t coff = (size_t)bz * sC;
    if (OUT == 0) Cf += coff; else Ch += coff;

    const uint32_t sb = smem_u32(smem);

    float acc[4][4][4];
#pragma unroll
    for (int i = 0; i < 4; i++)
#pragma unroll
        for (int j = 0; j < 4; j++)
#pragma unroll
            for (int q = 0; q < 4; q++) acc[i][j][q] = 0.f;

    const int Keff = KCAPQ ? kcap[bz] : K;
    const int nk = Keff >> 6;                        // 64-wide chunks

    const int s_row = tid >> 3, s_kt = tid & 7;
    uint32_t doff[4];
    int      srow[4];
#pragma unroll
    for (int h = 0; h < 4; h++) {
        const int r = s_row + h * 32;
        srow[h] = r;
        doff[h] = (uint32_t)((s_kt * 16 + (r >> 3)) * 128 + (r & 7) * 16);
    }

    auto issue = [&](int i) {
        const uint32_t s = sb + (uint32_t)(i % NSTG) * STAGE;
        const int k0 = i << 6;
#pragma unroll
        for (int h = 0; h < 4; h++) {
            const size_t ga = (size_t)(m0 + srow[h]) * K + k0 + s_kt * 8;
            const size_t gb = (size_t)(n0 + srow[h]) * K + k0 + s_kt * 8;
            cp16(s + doff[h],         A + ga);
            cp16(s + 16384 + doff[h], B + gb);
        }
        asm volatile("cp.async.commit_group;");
    };

    issue(0);
    issue(1);
    const int mrow16 = (lane & 7) * 16;
    const int bmi = (lane >> 3) & 1;
    const int dm = (lane >> 3) & 1, dk = lane >> 4;

    for (int i = 0; i < nk; i++) {
        if (i == nk - 1) asm volatile("cp.async.wait_group 0;");
        else             asm volatile("cp.async.wait_group 1;");
        __syncthreads();
        if (i + 2 < nk) issue(i + 2);

        const uint32_t st  = sb + (uint32_t)(i % NSTG) * STAGE;
        const uint32_t sAa = st;
        const uint32_t sBb = st + 16384;

#pragma unroll
        for (int ks = 0; ks < 4; ks++) {
            uint32_t a[4][4];
#pragma unroll
            for (int mt = 0; mt < 4; mt++) {
                const int mt8 = wm * 8 + mt * 2 + dm;
                ldmA(a[mt], sAa + toff(mt8, ks * 2 + dk) + mrow16);
            }
            uint32_t bh[4][2];
#pragma unroll
            for (int nt = 0; nt < 4; nt++)
                ldmB(bh[nt], sBb + toff(wn * 4 + nt, ks * 2 + bmi) + mrow16);
#pragma unroll
            for (int mt = 0; mt < 4; mt++)
#pragma unroll
                for (int nt = 0; nt < 4; nt++)
                    mma16816(acc[mt][nt], a[mt], bh[nt]);
        }
    }

    // ---------------- epilogue ----------------
    const int cq = (lane & 3) * 2, rq = lane >> 2;
#pragma unroll
    for (int nt = 0; nt < 4; nt++) {
        const int c = n0 + wn * 32 + nt * 8 + cq;
        float bv0 = 0.f, bv1 = 0.f;
        if (BIAS) { bv0 = bias[c]; bv1 = bias[c + 1]; }
#pragma unroll
        for (int mt = 0; mt < 4; mt++) {
            const int r0 = m0 + wm * 64 + mt * 16 + rq;
#pragma unroll
            for (int h = 0; h < 2; h++) {
                const int row = r0 + h * 8;
                float v0 = acc[mt][nt][h * 2 + 0] * alpha + bv0;
                float v1 = acc[mt][nt][h * 2 + 1] * alpha + bv1;
                if (RESID) {
                    float2 rv = *(const float2*)(resid + (size_t)row * N + c);
                    v0 += rv.x; v1 += rv.y;
                }
                if (RELU) { v0 = fmaxf(v0, 0.f); v1 = fmaxf(v1, 0.f); }
                if (OUT == 0) {
                    *(float2*)(Cf + (size_t)row * N + c) = make_float2(v0, v1);
                } else {
                    *(__half2*)(Ch + (size_t)row * N + c) =
                        __halves2half2(__float2half(v0), __float2half(v1));
                }
            }
        }
    }
}

// ---------------- mask prefix scan: idx / pos / cnt / cnt_pad per batch ----------------
__global__ void __launch_bounds__(1024) mask_scan(const int* __restrict__ mask,
                                                  int* __restrict__ idx,
                                                  int* __restrict__ pos,
                                                  int* __restrict__ cnt,
                                                  int* __restrict__ cpd)
{
    __shared__ int sc[1024];
    const int b = blockIdx.x, t = threadIdx.x;
    const int m0 = mask[b * NS + 2 * t];
    const int m1 = mask[b * NS + 2 * t + 1];
    const int s = m0 + m1;
    sc[t] = s;
    __syncthreads();
    for (int off = 1; off < 1024; off <<= 1) {
        int v = (t >= off) ? sc[t - off] : 0;
        __syncthreads();
        sc[t] += v;
        __syncthreads();
    }
    const int ex = sc[t] - s;
    pos[b * NS + 2 * t]     = ex;
    pos[b * NS + 2 * t + 1] = ex + m0;
    if (m0) idx[b * NS + ex]      = 2 * t;
    if (m1) idx[b * NS + ex + m0] = 2 * t + 1;
    if (t == 1023) {
        cnt[b] = sc[1023];
        cpd[b] = (sc[1023] + 127) & ~127;
    }
}

// ---------------- gather xn rows into packed layout (zero padding rows) ----------------
__global__ void __launch_bounds__(128) gather_xn(const __half* __restrict__ xn,
                                                 const int* __restrict__ idx,
                                                 const int* __restrict__ cnt,
                                                 const int* __restrict__ cpd,
                                                 __half* __restrict__ xnp)
{
    const int b = blockIdx.y;
    const int p = blockIdx.x;
    if (p >= cpd[b]) return;
    const int c = cnt[b];
    uint4* dst = (uint4*)(xnp + ((size_t)b * NS + p) * ND);
    if (p < c) {
        const uint4* src = (const uint4*)(xn + ((size_t)b * NS + idx[b * NS + p]) * ND);
        dst[threadIdx.x] = src[threadIdx.x];
    } else {
        dst[threadIdx.x] = make_uint4(0u, 0u, 0u, 0u);
    }
}

// ---------------- transpose packed k (kp -> ktp) ----------------
__global__ void __launch_bounds__(256) kt_only(const __half* __restrict__ kp,
                                               const int* __restrict__ cpd,
                                               __half* __restrict__ ktp)
{
    __shared__ __half tile[64][65];
    const int b = blockIdx.z;
    const int p0 = blockIdx.y * 64, d0 = blockIdx.x * 64;
    if (p0 >= cpd[b]) return;
    const size_t kb  = (size_t)b * NS * ND;
    const size_t ktb = (size_t)b * ND * NS;
    for (int u = threadIdx.x; u < 4096; u += 256) {
        const int rr = u >> 6, cc = u & 63;
        tile[rr][cc] = kp[kb + (size_t)(p0 + rr) * ND + d0 + cc];
    }
    __syncthreads();
    for (int u = threadIdx.x; u < 4096; u += 256) {
        const int rr = u >> 6, cc = u & 63;
        ktp[ktb + (size_t)(d0 + rr) * NS + p0 + cc] = tile[cc][rr];
    }
}

// ---------------- softmax over packed scores + scatter to full w + packed fp16 ----------------
__global__ void __launch_bounds__(256) softmax_scatter(
    float* __restrict__ wout,
    __half* __restrict__ wp,
    const int* __restrict__ mask,
    const int* __restrict__ pos,
    const int* __restrict__ cnt,
    const int* __restrict__ cpd)
{
    __shared__ float sm[NS];
    __shared__ float red[8];
    const int r = blockIdx.x;
    const int b = r >> 11;
    const int t = threadIdx.x;
    const int c = cnt[b], cp = cpd[b];
    float* p = wout + (size_t)r * NS;

    float mx = -3.4e38f;
    for (int j = t; j < c; j += 256) mx = fmaxf(mx, p[j]);
#pragma unroll
    for (int o = 16; o; o >>= 1) mx = fmaxf(mx, __shfl_xor_sync(0xffffffffu, mx, o));
    if ((t & 31) == 0) red[t >> 5] = mx;
    __syncthreads();
    mx = red[0];
#pragma unroll
    for (int i = 1; i < 8; i++) mx = fmaxf(mx, red[i]);
    __syncthreads();

    float s = 0.f;
    for (int j = t; j < c; j += 256) {
        const float e = __expf(p[j] - mx);
        sm[j] = e;
        s += e;
    }
#pragma unroll
    for (int o = 16; o; o >>= 1) s += __shfl_xor_sync(0xffffffffu, s, o);
    if ((t & 31) == 0) red[t >> 5] = s;
    __syncthreads();
    s = 0.f;
#pragma unroll
    for (int i = 0; i < 8; i++) s += red[i];
    const float inv = 1.f / s;

    __half* wpr = wp + (size_t)r * NS;
    for (int j = t; j < cp; j += 256)
        wpr[j] = __float2half(j < c ? sm[j] * inv : 0.f);

    const int* mrow = mask + (size_t)b * NS;
    const int* prow = pos  + (size_t)b * NS;
    for (int j = t; j < NS; j += 256)
        p[j] = mrow[j] ? sm[prow[j]] * inv : 0.f;
}

// ---------------- LayerNorm -> fp16 ----------------
__global__ void __launch_bounds__(256) ln_f16(const float* __restrict__ x,
                                              const float* __restrict__ g,
                                              const float* __restrict__ b,
                                              __half* __restrict__ o)
{
    size_t row = blockIdx.x;
    int t = threadIdx.x;
    float4 xv = ((const float4*)(x + row * ND))[t];
    float s  = xv.x + xv.y + xv.z + xv.w;
    float ss = xv.x*xv.x + xv.y*xv.y + xv.z*xv.z + xv.w*xv.w;
#pragma unroll
    for (int off = 16; off; off >>= 1) {
        s  += __shfl_xor_sync(0xffffffffu, s,  off);
        ss += __shfl_xor_sync(0xffffffffu, ss, off);
    }
    __shared__ float sh_s[8], sh_ss[8];
    if ((t & 31) == 0) { sh_s[t >> 5] = s; sh_ss[t >> 5] = ss; }
    __syncthreads();
    float ts = 0.f, tss = 0.f;
#pragma unroll
    for (int i = 0; i < 8; i++) { ts += sh_s[i]; tss += sh_ss[i]; }
    float mean = ts * (1.f / ND);
    float var  = tss * (1.f / ND) - mean * mean;
    float rstd = rsqrtf(var + 1e-5f);
    float4 gv = ((const float4*)g)[t];
    float4 bv = ((const float4*)b)[t];
    float o0 = (xv.x - mean) * rstd * gv.x + bv.x;
    float o1 = (xv.y - mean) * rstd * gv.y + bv.y;
    float o2 = (xv.z - mean) * rstd * gv.z + bv.z;
    float o3 = (xv.w - mean) * rstd * gv.w + bv.w;
    __half2* ph = (__half2*)(o + row * ND);
    ph[2*t]   = __halves2half2(__float2half(o0), __float2half(o1));
    ph[2*t+1] = __halves2half2(__float2half(o2), __float2half(o3));
}

// ---------------- 5 weight transposes in ONE launch ----------------
__global__ void __launch_bounds__(256) wt_conv5(
    const float* __restrict__ W0, const float* __restrict__ W1,
    const float* __restrict__ W2, const float* __restrict__ W3,
    const float* __restrict__ W4, __half* __restrict__ T)
{
    const float* W;
    switch (blockIdx.z) {
        case 0: W = W0; break;
        case 1: W = W1; break;
        case 2: W = W2; break;
        case 3: W = W3; break;
        default: W = W4; break;
    }
    __half* Th = T + (size_t)blockIdx.z * WSZ;
    __shared__ float tile[64][65];
    int k0 = blockIdx.y * 64, n0 = blockIdx.x * 64;
#pragma unroll
    for (int u = threadIdx.x; u < 4096; u += 256) {
        int r = u >> 6, c = u & 63;
        tile[r][c] = W[(size_t)(k0 + r) * ND + n0 + c];
    }
    __syncthreads();
#pragma unroll
    for (int u = threadIdx.x; u < 4096; u += 256) {
        int r = u >> 6, c = u & 63;
        Th[(size_t)(n0 + r) * ND + k0 + c] = __float2half(tile[c][r]);
    }
}

// ---------------- driver ----------------
extern "C" void kernel_launch(void* const* d_in, const int* in_sizes, int n_in,
                              void* d_out, int out_size)
{
    const float* x    = (const float*)d_in[0];
    const int*   mask = (const int*)  d_in[1];
    const float* ln1g = (const float*)d_in[2];
    const float* ln1b = (const float*)d_in[3];
    const float* Wq   = (const float*)d_in[4];
    const float* bq   = (const float*)d_in[5];
    const float* Wk   = (const float*)d_in[6];
    const float* bk   = (const float*)d_in[7];
    const float* Wo   = (const float*)d_in[8];
    const float* bo   = (const float*)d_in[9];
    const float* ln2g = (const float*)d_in[10];
    const float* ln2b = (const float*)d_in[11];
    const float* W1   = (const float*)d_in[12];
    const float* b1   = (const float*)d_in[13];
    const float* W2   = (const float*)d_in[14];
    const float* b2   = (const float*)d_in[15];

    float* out  = (float*)d_out;
    float* wout = out + (size_t)NROWS * ND;

    __half *xn, *xnp, *q, *kp, *ktp, *wp, *at, *xn2, *h, *wt;
    float* x2;
    int *idx, *pos, *cnt, *cpd;
    cudaGetSymbolAddress((void**)&xn,  g_xn);
    cudaGetSymbolAddress((void**)&xnp, g_xnp);
    cudaGetSymbolAddress((void**)&q,   g_q);
    cudaGetSymbolAddress((void**)&kp,  g_kp);
    cudaGetSymbolAddress((void**)&ktp, g_ktp);
    cudaGetSymbolAddress((void**)&wp,  g_wp);
    cudaGetSymbolAddress((void**)&at,  g_at);
    cudaGetSymbolAddress((void**)&xn2, g_xn2);
    cudaGetSymbolAddress((void**)&h,   g_h);
    cudaGetSymbolAddress((void**)&x2,  g_x2);
    cudaGetSymbolAddress((void**)&wt,  g_wt);
    cudaGetSymbolAddress((void**)&idx, g_idx);
    cudaGetSymbolAddress((void**)&pos, g_pos);
    cudaGetSymbolAddress((void**)&cnt, g_cnt);
    cudaGetSymbolAddress((void**)&cpd, g_cpd);

    __half *wq_t = wt + 0*WSZ;
    __half *wk_t = wt + 1*WSZ;
    __half *wo_t = wt + 2*WSZ;
    __half *w1_t = wt + 3*WSZ;
    __half *w2_t = wt + 4*WSZ;

    cudaFuncSetAttribute(gemm_tc<true,false,false,1,false,false,false>,
                         cudaFuncAttributeMaxDynamicSharedMemorySize, SMEMSZ);
    cudaFuncSetAttribute(gemm_tc<true,false,false,1,false,false,true>,
                         cudaFuncAttributeMaxDynamicSharedMemorySize, SMEMSZ);
    cudaFuncSetAttribute(gemm_tc<false,false,false,0,true,false,false>,
                         cudaFuncAttributeMaxDynamicSharedMemorySize, SMEMSZ);
    cudaFuncSetAttribute(gemm_tc<false,false,false,1,false,true,false>,
                         cudaFuncAttributeMaxDynamicSharedMemorySize, SMEMSZ);
    cudaFuncSetAttribute(gemm_tc<true,false,true,0,false,false,false>,
                         cudaFuncAttributeMaxDynamicSharedMemorySize, SMEMSZ);
    cudaFuncSetAttribute(gemm_tc<true,true,false,1,false,false,false>,
                         cudaFuncAttributeMaxDynamicSharedMemorySize, SMEMSZ);

    // weight transposes + mask scan (independent of GEMMs)
    wt_conv5<<<dim3(16, 16, 5), 256>>>(Wq, Wk, Wo, W1, W2, wt);
    mask_scan<<<NB, 1024>>>(mask, idx, pos, cnt, cpd);

    // 1) xn = LN1(x)
    ln_f16<<<NROWS, 256>>>(x, ln1g, ln1b, xn);

    // 2) packed xn rows for k projection
    gather_xn<<<dim3(NS, NB), 128>>>(xn, idx, cnt, cpd, xnp);

    dim3 gP(ND / 128, NROWS / 128, 1);
    // 3) q = xn@Wq+bq (full)
    gemm_tc<true,false,false,1,false,false,false><<<gP, 256, SMEMSZ>>>(
        xn, wq_t, NROWS, ND, ND, 0, 0, 0,
        nullptr, q, bq, nullptr, nullptr, nullptr, nullptr, 1.f);

    // 4) kp = xnp@Wk+bk  (batched, M-capped: only packed rows; v == k faithful bug)
    dim3 gK(ND / 128, NS / 128, NB);
    gemm_tc<true,false,false,1,false,false,true><<<gK, 256, SMEMSZ>>>(
        xnp, wk_t, NS, ND, ND,
        (long long)NS * ND, 0, (long long)NS * ND,
        nullptr, kp, bk, nullptr, nullptr, nullptr, cpd, 1.f);

    // 5) packed kT
    kt_only<<<dim3(ND / 64, NS / 64, NB), 256>>>(kp, cpd, ktp);

    // 6) packed scores = (q @ kp^T)/32 -> wout packed cols (fp32)
    dim3 gS(NS / 128, NS / 128, NB);
    gemm_tc<false,false,false,0,true,false,false><<<gS, 256, SMEMSZ>>>(
        q, kp, NS, NS, ND,
        (long long)NS * ND, (long long)NS * ND, (long long)NS * NS,
        wout, nullptr, nullptr, nullptr, cpd, nullptr, nullptr, 0.03125f);

    // 7) softmax over packed + scatter full w + packed fp16 w
    softmax_scatter<<<NROWS, 256>>>(wout, wp, mask, pos, cnt, cpd);

    // 8) attn = wp @ ktp^T  (K = cnt_pad per batch)
    dim3 gA(ND / 128, NS / 128, NB);
    gemm_tc<false,false,false,1,false,true,false><<<gA, 256, SMEMSZ>>>(
        wp, ktp, NS, ND, NS,
        (long long)NS * NS, (long long)ND * NS, (long long)NS * ND,
        nullptr, at, nullptr, nullptr, nullptr, cpd, nullptr, 1.f);

    // 9) x2 = x + attn @ Wo + bo
    gemm_tc<true,false,true,0,false,false,false><<<gP, 256, SMEMSZ>>>(
        at, wo_t, NROWS, ND, ND, 0, 0, 0,
        x2, nullptr, bo, x, nullptr, nullptr, nullptr, 1.f);

    // 10) xn2 = LN2(x2)
    ln_f16<<<NROWS, 256>>>(x2, ln2g, ln2b, xn2);

    // 11) h = relu(xn2 @ W1 + b1)
    gemm_tc<true,true,false,1,false,false,false><<<gP, 256, SMEMSZ>>>(
        xn2, w1_t, NROWS, ND, ND, 0, 0, 0,
        nullptr, h, b1, nullptr, nullptr, nullptr, nullptr, 1.f);

    // 12) out = x2 + h @ W2 + b2
    gemm_tc<true,false,true,0,false,false,false><<<gP, 256, SMEMSZ>>>(
        h, w2_t, NROWS, ND, ND, 0, 0, 0,
        out, nullptr, b2, x2, nullptr, nullptr, nullptr, 1.f);
}

// round 16
// speedup vs baseline: 1.2966x; 1.0026x over previous
#include <cuda_runtime.h>
#include <cuda_fp16.h>
#include <stdint.h>

#define NB 8
#define NS 2048
#define ND 1024
#define NROWS (NB * NS)          // 16384
#define WSZ ((size_t)ND * ND)

// ---------------- scratch (no cudaMalloc allowed) ----------------
__device__ __half g_xn  [(size_t)NROWS * ND];
__device__ __half g_xnp [(size_t)NROWS * ND];    // packed xn rows (padding stays zero)
__device__ __half g_q   [(size_t)NROWS * ND];
__device__ __half g_kp  [(size_t)NROWS * ND];    // packed k rows (per batch)
__device__ __half g_ktp [(size_t)NROWS * ND];    // packed k transposed [ND x NS]
__device__ __half g_wp  [(size_t)NB * NS * NS];  // packed softmax fp16
__device__ __half g_at  [(size_t)NROWS * ND];
__device__ float  g_x2  [(size_t)NROWS * ND];
__device__ __half g_xn2 [(size_t)NROWS * ND];
__device__ __half g_h   [(size_t)NROWS * ND];
__device__ __half g_wt  [5 * WSZ];
__device__ int    g_idx [NB * NS];
__device__ int    g_pos [NB * NS];
__device__ int    g_cnt [NB];
__device__ int    g_cpd [NB];

// ---------------- helpers ----------------
__device__ __forceinline__ uint32_t smem_u32(const void* p) {
    uint32_t a;
    asm("{ .reg .u64 t; cvta.to.shared.u64 t, %1; cvt.u32.u64 %0, t; }" : "=r"(a) : "l"(p));
    return a;
}
__device__ __forceinline__ void cp16(uint32_t dst, const void* src) {
    asm volatile("cp.async.cg.shared.global [%0], [%1], 16;" :: "r"(dst), "l"(src));
}
__device__ __forceinline__ void ldmA(uint32_t* a, uint32_t addr) {
    asm volatile("ldmatrix.sync.aligned.m8n8.x4.shared.b16 {%0,%1,%2,%3}, [%4];"
                 : "=r"(a[0]), "=r"(a[1]), "=r"(a[2]), "=r"(a[3]) : "r"(addr));
}
__device__ __forceinline__ void ldmB(uint32_t* b, uint32_t addr) {
    asm volatile("ldmatrix.sync.aligned.m8n8.x2.shared.b16 {%0,%1}, [%2];"
                 : "=r"(b[0]), "=r"(b[1]) : "r"(addr));
}
__device__ __forceinline__ void mma16816(float* c, const uint32_t* a, const uint32_t* b) {
    asm volatile("mma.sync.aligned.m16n8k16.row.col.f32.f16.f16.f32 "
                 "{%0,%1,%2,%3}, {%4,%5,%6,%7}, {%8,%9}, {%0,%1,%2,%3};"
                 : "+f"(c[0]), "+f"(c[1]), "+f"(c[2]), "+f"(c[3])
                 : "r"(a[0]), "r"(a[1]), "r"(a[2]), "r"(a[3]), "r"(b[0]), "r"(b[1]));
}

#define NSTG 3
#define STAGE 32768u               // A 16K | B 16K  (kchunk = 64)
#define SMEMSZ (NSTG * STAGE)      // 96 KB -> 2 CTAs/SM
__device__ __forceinline__ uint32_t toff(int rt8, int kt8) {
    return (uint32_t)((kt8 * 16 + rt8) * 128);
}

// ---------------- shared GEMM mainloop: 128x128 tile, kchunk 64, 1 pass ----------------
// D = alpha * A[128 rows @ m0, K] * B[128 rows @ n0, K]^T (+bias) (+resid) (relu)
template <bool BIAS, bool RELU, bool RESID, int OUT>
__device__ __forceinline__ void gemm_core(
    const __half* __restrict__ A, const __half* __restrict__ B,
    int N, int K, int nk, int m0, int n0, char* smem,
    float* __restrict__ Cf, __half* __restrict__ Ch,
    const float* __restrict__ bias, const float* __restrict__ resid, float alpha)
{
    const int tid  = threadIdx.x;
    const int lane = tid & 31, wid = tid >> 5;
    const int wm = wid & 1, wn = wid >> 1;          // 2 x 4 warp grid, warp tile 64x32
    const uint32_t sb = smem_u32(smem);

    float acc[4][4][4];
#pragma unroll
    for (int i = 0; i < 4; i++)
#pragma unroll
        for (int j = 0; j < 4; j++)
#pragma unroll
            for (int q = 0; q < 4; q++) acc[i][j][q] = 0.f;

    const int s_row = tid >> 3, s_kt = tid & 7;
    uint32_t doff[4];
    int      srow[4];
#pragma unroll
    for (int h = 0; h < 4; h++) {
        const int r = s_row + h * 32;
        srow[h] = r;
        doff[h] = (uint32_t)((s_kt * 16 + (r >> 3)) * 128 + (r & 7) * 16);
    }

    auto issue = [&](int i) {
        const uint32_t s = sb + (uint32_t)(i % NSTG) * STAGE;
        const int k0 = i << 6;
#pragma unroll
        for (int h = 0; h < 4; h++) {
            const size_t ga = (size_t)(m0 + srow[h]) * K + k0 + s_kt * 8;
            const size_t gb = (size_t)(n0 + srow[h]) * K + k0 + s_kt * 8;
            cp16(s + doff[h],         A + ga);
            cp16(s + 16384 + doff[h], B + gb);
        }
        asm volatile("cp.async.commit_group;");
    };

    issue(0);
    issue(1);
    const int mrow16 = (lane & 7) * 16;
    const int bmi = (lane >> 3) & 1;
    const int dm = (lane >> 3) & 1, dk = lane >> 4;

    for (int i = 0; i < nk; i++) {
        if (i == nk - 1) asm volatile("cp.async.wait_group 0;");
        else             asm volatile("cp.async.wait_group 1;");
        __syncthreads();
        if (i + 2 < nk) issue(i + 2);

        const uint32_t st  = sb + (uint32_t)(i % NSTG) * STAGE;
        const uint32_t sAa = st;
        const uint32_t sBb = st + 16384;

#pragma unroll
        for (int ks = 0; ks < 4; ks++) {
            uint32_t a[4][4];
#pragma unroll
            for (int mt = 0; mt < 4; mt++) {
                const int mt8 = wm * 8 + mt * 2 + dm;
                ldmA(a[mt], sAa + toff(mt8, ks * 2 + dk) + mrow16);
            }
            uint32_t bh[4][2];
#pragma unroll
            for (int nt = 0; nt < 4; nt++)
                ldmB(bh[nt], sBb + toff(wn * 4 + nt, ks * 2 + bmi) + mrow16);
#pragma unroll
            for (int mt = 0; mt < 4; mt++)
#pragma unroll
                for (int nt = 0; nt < 4; nt++)
                    mma16816(acc[mt][nt], a[mt], bh[nt]);
        }
    }

    const int cq = (lane & 3) * 2, rq = lane >> 2;
#pragma unroll
    for (int nt = 0; nt < 4; nt++) {
        const int c = n0 + wn * 32 + nt * 8 + cq;
        float bv0 = 0.f, bv1 = 0.f;
        if (BIAS) { bv0 = bias[c]; bv1 = bias[c + 1]; }
#pragma unroll
        for (int mt = 0; mt < 4; mt++) {
            const int r0 = m0 + wm * 64 + mt * 16 + rq;
#pragma unroll
            for (int h = 0; h < 2; h++) {
                const int row = r0 + h * 8;
                float v0 = acc[mt][nt][h * 2 + 0] * alpha + bv0;
                float v1 = acc[mt][nt][h * 2 + 1] * alpha + bv1;
                if (RESID) {
                    float2 rv = *(const float2*)(resid + (size_t)row * N + c);
                    v0 += rv.x; v1 += rv.y;
                }
                if (RELU) { v0 = fmaxf(v0, 0.f); v1 = fmaxf(v1, 0.f); }
                if (OUT == 0) {
                    *(float2*)(Cf + (size_t)row * N + c) = make_float2(v0, v1);
                } else {
                    *(__half2*)(Ch + (size_t)row * N + c) =
                        __halves2half2(__float2half(v0), __float2half(v1));
                }
            }
        }
    }
}

// ---------------- generic GEMM wrapper ----------------
template <bool BIAS, bool RELU, bool RESID, int OUT, bool NCAPQ, bool KCAPQ>
__global__ void __launch_bounds__(256, 2) gemm_tc(
    const __half* __restrict__ A,
    const __half* __restrict__ B,
    int M, int N, int K,
    long long sA, long long sB, long long sC,
    float* __restrict__ Cf,
    __half* __restrict__ Ch,
    const float* __restrict__ bias,
    const float* __restrict__ resid,
    const int* __restrict__ ncap,
    const int* __restrict__ kcap,
    float alpha)
{
    extern __shared__ char smem[];
    const int bz = blockIdx.z;
    const int n0 = blockIdx.x * 128;
    const int m0 = blockIdx.y * 128;
    if (NCAPQ && n0 >= ncap[bz]) return;
    A += (size_t)bz * sA; B += (size_t)bz * sB;
    const size_t coff = (size_t)bz * sC;
    if (OUT == 0) Cf += coff; else Ch += coff;
    const int Keff = KCAPQ ? kcap[bz] : K;
    gemm_core<BIAS, RELU, RESID, OUT>(A, B, N, K, Keff >> 6, m0, n0, smem,
                                      Cf, Ch, bias, resid, alpha);
}

// ---------------- fused q + packed-k projection (one launch) ----------------
// z == 0 : q = xn @ Wq^T + bq  (full M, y in 0..127)
// z >= 1 : kp[b] = xnp[b] @ Wk^T + bk  (b = z-1, y < 16, m0 < cpd[b])
__global__ void __launch_bounds__(256, 2) gemm_qk(
    const __half* __restrict__ xn,  const __half* __restrict__ xnp,
    const __half* __restrict__ wq,  const __half* __restrict__ wk,
    __half* __restrict__ q,         __half* __restrict__ kp,
    const float* __restrict__ bq,   const float* __restrict__ bk,
    const int* __restrict__ cpd)
{
    extern __shared__ char smem[];
    const int bz = blockIdx.z;
    const int m0 = blockIdx.y * 128;
    const int n0 = blockIdx.x * 128;
    const __half *A, *B;
    __half* C;
    const float* bias;
    if (bz == 0) {
        A = xn; B = wq; C = q; bias = bq;
    } else {
        if (blockIdx.y >= 16) return;
        const int b = bz - 1;
        if (m0 >= cpd[b]) return;
        A = xnp + (size_t)b * NS * ND;
        C = kp  + (size_t)b * NS * ND;
        B = wk; bias = bk;
    }
    gemm_core<true, false, false, 1>(A, B, ND, ND, ND >> 6, m0, n0, smem,
                                     nullptr, C, bias, nullptr, 1.f);
}

// ---------------- mask prefix scan ----------------
__global__ void __launch_bounds__(1024) mask_scan(const int* __restrict__ mask,
                                                  int* __restrict__ idx,
                                                  int* __restrict__ pos,
                                                  int* __restrict__ cnt,
                                                  int* __restrict__ cpd)
{
    __shared__ int sc[1024];
    const int b = blockIdx.x, t = threadIdx.x;
    const int m0 = mask[b * NS + 2 * t];
    const int m1 = mask[b * NS + 2 * t + 1];
    const int s = m0 + m1;
    sc[t] = s;
    __syncthreads();
    for (int off = 1; off < 1024; off <<= 1) {
        int v = (t >= off) ? sc[t - off] : 0;
        __syncthreads();
        sc[t] += v;
        __syncthreads();
    }
    const int ex = sc[t] - s;
    pos[b * NS + 2 * t]     = ex;
    pos[b * NS + 2 * t + 1] = ex + m0;
    if (m0) idx[b * NS + ex]      = 2 * t;
    if (m1) idx[b * NS + ex + m0] = 2 * t + 1;
    if (t == 1023) {
        cnt[b] = sc[1023];
        cpd[b] = (sc[1023] + 127) & ~127;
    }
}

// ---------------- LN1 fused: writes xn + packed xnp (padding rows stay zero) ----------------
__global__ void __launch_bounds__(256) ln1_fused(const float* __restrict__ x,
                                                 const float* __restrict__ g,
                                                 const float* __restrict__ b,
                                                 const int* __restrict__ mask,
                                                 const int* __restrict__ pos,
                                                 __half* __restrict__ xn,
                                                 __half* __restrict__ xnp)
{
    size_t row = blockIdx.x;
    int t = threadIdx.x;
    float4 xv = ((const float4*)(x + row * ND))[t];
    float s  = xv.x + xv.y + xv.z + xv.w;
    float ss = xv.x*xv.x + xv.y*xv.y + xv.z*xv.z + xv.w*xv.w;
#pragma unroll
    for (int off = 16; off; off >>= 1) {
        s  += __shfl_xor_sync(0xffffffffu, s,  off);
        ss += __shfl_xor_sync(0xffffffffu, ss, off);
    }
    __shared__ float sh_s[8], sh_ss[8];
    if ((t & 31) == 0) { sh_s[t >> 5] = s; sh_ss[t >> 5] = ss; }
    __syncthreads();
    float ts = 0.f, tss = 0.f;
#pragma unroll
    for (int i = 0; i < 8; i++) { ts += sh_s[i]; tss += sh_ss[i]; }
    float mean = ts * (1.f / ND);
    float var  = tss * (1.f / ND) - mean * mean;
    float rstd = rsqrtf(var + 1e-5f);
    float4 gv = ((const float4*)g)[t];
    float4 bv = ((const float4*)b)[t];
    float o0 = (xv.x - mean) * rstd * gv.x + bv.x;
    float o1 = (xv.y - mean) * rstd * gv.y + bv.y;
    float o2 = (xv.z - mean) * rstd * gv.z + bv.z;
    float o3 = (xv.w - mean) * rstd * gv.w + bv.w;
    __half2 h01 = __halves2half2(__float2half(o0), __float2half(o1));
    __half2 h23 = __halves2half2(__float2half(o2), __float2half(o3));
    __half2* ph = (__half2*)(xn + row * ND);
    ph[2*t]   = h01;
    ph[2*t+1] = h23;
    const int bb = (int)(row >> 11), j = (int)(row & 2047);
    if (mask[bb * NS + j]) {
        const size_t pr = (size_t)bb * NS + pos[bb * NS + j];
        __half2* pp = (__half2*)(xnp + pr * ND);
        pp[2*t]   = h01;
        pp[2*t+1] = h23;
    }
}

// ---------------- plain LayerNorm -> fp16 (LN2) ----------------
__global__ void __launch_bounds__(256) ln_f16(const float* __restrict__ x,
                                              const float* __restrict__ g,
                                              const float* __restrict__ b,
                                              __half* __restrict__ o)
{
    size_t row = blockIdx.x;
    int t = threadIdx.x;
    float4 xv = ((const float4*)(x + row * ND))[t];
    float s  = xv.x + xv.y + xv.z + xv.w;
    float ss = xv.x*xv.x + xv.y*xv.y + xv.z*xv.z + xv.w*xv.w;
#pragma unroll
    for (int off = 16; off; off >>= 1) {
        s  += __shfl_xor_sync(0xffffffffu, s,  off);
        ss += __shfl_xor_sync(0xffffffffu, ss, off);
    }
    __shared__ float sh_s[8], sh_ss[8];
    if ((t & 31) == 0) { sh_s[t >> 5] = s; sh_ss[t >> 5] = ss; }
    __syncthreads();
    float ts = 0.f, tss = 0.f;
#pragma unroll
    for (int i = 0; i < 8; i++) { ts += sh_s[i]; tss += sh_ss[i]; }
    float mean = ts * (1.f / ND);
    float var  = tss * (1.f / ND) - mean * mean;
    float rstd = rsqrtf(var + 1e-5f);
    float4 gv = ((const float4*)g)[t];
    float4 bv = ((const float4*)b)[t];
    float o0 = (xv.x - mean) * rstd * gv.x + bv.x;
    float o1 = (xv.y - mean) * rstd * gv.y + bv.y;
    float o2 = (xv.z - mean) * rstd * gv.z + bv.z;
    float o3 = (xv.w - mean) * rstd * gv.w + bv.w;
    __half2* ph = (__half2*)(o + row * ND);
    ph[2*t]   = __halves2half2(__float2half(o0), __float2half(o1));
    ph[2*t+1] = __halves2half2(__float2half(o2), __float2half(o3));
}

// ---------------- transpose packed k (kp -> ktp) ----------------
__global__ void __launch_bounds__(256) kt_only(const __half* __restrict__ kp,
                                               const int* __restrict__ cpd,
                                               __half* __restrict__ ktp)
{
    __shared__ __half tile[64][65];
    const int b = blockIdx.z;
    const int p0 = blockIdx.y * 64, d0 = blockIdx.x * 64;
    if (p0 >= cpd[b]) return;
    const size_t kb  = (size_t)b * NS * ND;
    const size_t ktb = (size_t)b * ND * NS;
    for (int u = threadIdx.x; u < 4096; u += 256) {
        const int rr = u >> 6, cc = u & 63;
        tile[rr][cc] = kp[kb + (size_t)(p0 + rr) * ND + d0 + cc];
    }
    __syncthreads();
    for (int u = threadIdx.x; u < 4096; u += 256) {
        const int rr = u >> 6, cc = u & 63;
        ktp[ktb + (size_t)(d0 + rr) * NS + p0 + cc] = tile[cc][rr];
    }
}

// ---------------- softmax over packed scores + scatter full w + packed fp16 ----------------
__global__ void __launch_bounds__(256) softmax_scatter(
    float* __restrict__ wout,
    __half* __restrict__ wp,
    const int* __restrict__ mask,
    const int* __restrict__ pos,
    const int* __restrict__ cnt,
    const int* __restrict__ cpd)
{
    __shared__ float sm[NS];
    __shared__ float red[8];
    const int r = blockIdx.x;
    const int b = r >> 11;
    const int t = threadIdx.x;
    const int c = cnt[b], cp = cpd[b];
    float* p = wout + (size_t)r * NS;

    float mx = -3.4e38f;
    for (int j = t; j < c; j += 256) mx = fmaxf(mx, p[j]);
#pragma unroll
    for (int o = 16; o; o >>= 1) mx = fmaxf(mx, __shfl_xor_sync(0xffffffffu, mx, o));
    if ((t & 31) == 0) red[t >> 5] = mx;
    __syncthreads();
    mx = red[0];
#pragma unroll
    for (int i = 1; i < 8; i++) mx = fmaxf(mx, red[i]);
    __syncthreads();

    float s = 0.f;
    for (int j = t; j < c; j += 256) {
        const float e = __expf(p[j] - mx);
        sm[j] = e;
        s += e;
    }
#pragma unroll
    for (int o = 16; o; o >>= 1) s += __shfl_xor_sync(0xffffffffu, s, o);
    if ((t & 31) == 0) red[t >> 5] = s;
    __syncthreads();
    s = 0.f;
#pragma unroll
    for (int i = 0; i < 8; i++) s += red[i];
    const float inv = 1.f / s;

    __half* wpr = wp + (size_t)r * NS;
    for (int j = t; j < cp; j += 256)
        wpr[j] = __float2half(j < c ? sm[j] * inv : 0.f);

    const int* mrow = mask + (size_t)b * NS;
    const int* prow = pos  + (size_t)b * NS;
    for (int j = t; j < NS; j += 256)
        p[j] = mrow[j] ? sm[prow[j]] * inv : 0.f;
}

// ---------------- 5 weight transposes in ONE launch ----------------
__global__ void __launch_bounds__(256) wt_conv5(
    const float* __restrict__ W0, const float* __restrict__ W1,
    const float* __restrict__ W2, const float* __restrict__ W3,
    const float* __restrict__ W4, __half* __restrict__ T)
{
    const float* W;
    switch (blockIdx.z) {
        case 0: W = W0; break;
        case 1: W = W1; break;
        case 2: W = W2; break;
        case 3: W = W3; break;
        default: W = W4; break;
    }
    __half* Th = T + (size_t)blockIdx.z * WSZ;
    __shared__ float tile[64][65];
    int k0 = blockIdx.y * 64, n0 = blockIdx.x * 64;
#pragma unroll
    for (int u = threadIdx.x; u < 4096; u += 256) {
        int r = u >> 6, c = u & 63;
        tile[r][c] = W[(size_t)(k0 + r) * ND + n0 + c];
    }
    __syncthreads();
#pragma unroll
    for (int u = threadIdx.x; u < 4096; u += 256) {
        int r = u >> 6, c = u & 63;
        Th[(size_t)(n0 + r) * ND + k0 + c] = __float2half(tile[c][r]);
    }
}

// ---------------- driver ----------------
extern "C" void kernel_launch(void* const* d_in, const int* in_sizes, int n_in,
                              void* d_out, int out_size)
{
    const float* x    = (const float*)d_in[0];
    const int*   mask = (const int*)  d_in[1];
    const float* ln1g = (const float*)d_in[2];
    const float* ln1b = (const float*)d_in[3];
    const float* Wq   = (const float*)d_in[4];
    const float* bq   = (const float*)d_in[5];
    const float* Wk   = (const float*)d_in[6];
    const float* bk   = (const float*)d_in[7];
    const float* Wo   = (const float*)d_in[8];
    const float* bo   = (const float*)d_in[9];
    const float* ln2g = (const float*)d_in[10];
    const float* ln2b = (const float*)d_in[11];
    const float* W1   = (const float*)d_in[12];
    const float* b1   = (const float*)d_in[13];
    const float* W2   = (const float*)d_in[14];
    const float* b2   = (const float*)d_in[15];

    float* out  = (float*)d_out;
    float* wout = out + (size_t)NROWS * ND;

    __half *xn, *xnp, *q, *kp, *ktp, *wp, *at, *xn2, *h, *wt;
    float* x2;
    int *idx, *pos, *cnt, *cpd;
    cudaGetSymbolAddress((void**)&xn,  g_xn);
    cudaGetSymbolAddress((void**)&xnp, g_xnp);
    cudaGetSymbolAddress((void**)&q,   g_q);
    cudaGetSymbolAddress((void**)&kp,  g_kp);
    cudaGetSymbolAddress((void**)&ktp, g_ktp);
    cudaGetSymbolAddress((void**)&wp,  g_wp);
    cudaGetSymbolAddress((void**)&at,  g_at);
    cudaGetSymbolAddress((void**)&xn2, g_xn2);
    cudaGetSymbolAddress((void**)&h,   g_h);
    cudaGetSymbolAddress((void**)&x2,  g_x2);
    cudaGetSymbolAddress((void**)&wt,  g_wt);
    cudaGetSymbolAddress((void**)&idx, g_idx);
    cudaGetSymbolAddress((void**)&pos, g_pos);
    cudaGetSymbolAddress((void**)&cnt, g_cnt);
    cudaGetSymbolAddress((void**)&cpd, g_cpd);

    __half *wq_t = wt + 0*WSZ;
    __half *wk_t = wt + 1*WSZ;
    __half *wo_t = wt + 2*WSZ;
    __half *w1_t = wt + 3*WSZ;
    __half *w2_t = wt + 4*WSZ;

    cudaFuncSetAttribute(gemm_qk,
                         cudaFuncAttributeMaxDynamicSharedMemorySize, SMEMSZ);
    cudaFuncSetAttribute(gemm_tc<false,false,false,0,true,false>,
                         cudaFuncAttributeMaxDynamicSharedMemorySize, SMEMSZ);
    cudaFuncSetAttribute(gemm_tc<false,false,false,1,false,true>,
                         cudaFuncAttributeMaxDynamicSharedMemorySize, SMEMSZ);
    cudaFuncSetAttribute(gemm_tc<true,false,true,0,false,false>,
                         cudaFuncAttributeMaxDynamicSharedMemorySize, SMEMSZ);
    cudaFuncSetAttribute(gemm_tc<true,true,false,1,false,false>,
                         cudaFuncAttributeMaxDynamicSharedMemorySize, SMEMSZ);

    // weight transposes + mask scan (independent of GEMMs)
    wt_conv5<<<dim3(16, 16, 5), 256>>>(Wq, Wk, Wo, W1, W2, wt);
    mask_scan<<<NB, 1024>>>(mask, idx, pos, cnt, cpd);

    // 1) xn = LN1(x), fused packed-row scatter into xnp
    ln1_fused<<<NROWS, 256>>>(x, ln1g, ln1b, mask, pos, xn, xnp);

    // 2) q (full) + kp (packed, batched) in ONE launch (v == k, faithful bug)
    gemm_qk<<<dim3(ND / 128, NROWS / 128, 1 + NB), 256, SMEMSZ>>>(
        xn, xnp, wq_t, wk_t, q, kp, bq, bk, cpd);

    // 3) packed kT
    kt_only<<<dim3(ND / 64, NS / 64, NB), 256>>>(kp, cpd, ktp);

    // 4) packed scores = (q @ kp^T)/32 -> wout packed cols (fp32)
    dim3 gS(NS / 128, NS / 128, NB);
    gemm_tc<false,false,false,0,true,false><<<gS, 256, SMEMSZ>>>(
        q, kp, NS, NS, ND,
        (long long)NS * ND, (long long)NS * ND, (long long)NS * NS,
        wout, nullptr, nullptr, nullptr, cpd, nullptr, 0.03125f);

    // 5) softmax over packed + scatter full w + packed fp16 w
    softmax_scatter<<<NROWS, 256>>>(wout, wp, mask, pos, cnt, cpd);

    // 6) attn = wp @ ktp^T  (K = cnt_pad per batch)
    dim3 gA(ND / 128, NS / 128, NB);
    gemm_tc<false,false,false,1,false,true><<<gA, 256, SMEMSZ>>>(
        wp, ktp, NS, ND, NS,
        (long long)NS * NS, (long long)ND * NS, (long long)NS * ND,
        nullptr, at, nullptr, nullptr, nullptr, cpd, 1.f);

    dim3 gP(ND / 128, NROWS / 128, 1);
    // 7) x2 = x + attn @ Wo + bo
    gemm_tc<true,false,true,0,false,false><<<gP, 256, SMEMSZ>>>(
        at, wo_t, NROWS, ND, ND, 0, 0, 0,
        x2, nullptr, bo, x, nullptr, nullptr, 1.f);

    // 8) xn2 = LN2(x2)
    ln_f16<<<NROWS, 256>>>(x2, ln2g, ln2b, xn2);

    // 9) h = relu(xn2 @ W1 + b1)
    gemm_tc<true,true,false,1,false,false><<<gP, 256, SMEMSZ>>>(
        xn2, w1_t, NROWS, ND, ND, 0, 0, 0,
        nullptr, h, b1, nullptr, nullptr, nullptr, 1.f);

    // 10) out = x2 + h @ W2 + b2
    gemm_tc<true,false,true,0,false,false><<<gP, 256, SMEMSZ>>>(
        h, w2_t, NROWS, ND, ND, 0, 0, 0,
        out, nullptr, b2, x2, nullptr, nullptr, 1.f);
}